// round 10
// baseline (speedup 1.0000x reference)
#include <cuda_runtime.h>
#include <cuda_fp16.h>
#include <mma.h>
#include <math.h>

using namespace nvcuda;

#define NN 100000
#define EE 1600000
#define FD 128
#define HD 64

// Scratch (device globals)
__device__ int    g_cnt[2 * NN + 32];       // [0..NN)=out, [NN..2NN)=in, [2NN]=scan ticket
__device__ float  g_nsrc[NN];
__device__ float  g_ndst[NN];
__device__ int    g_off[NN];
__device__ int    g_cursor[NN];
__device__ int    g_csr[EE];
__device__ __half g_x16[(size_t)NN * HD];   // x = (feat*nsrc)@W1 (fp16)
__device__ __half g_y16[(size_t)NN * HD];   // y = relu(agg1*ndst+b1)*nsrc (fp16)

// ---------------------------------------------------------------------------
// Degrees (R4-proven: 4 edges/thread)
// ---------------------------------------------------------------------------
__global__ void deg_kernel(const int* __restrict__ src, const int* __restrict__ dst, int E) {
    int i = (blockIdx.x * blockDim.x + threadIdx.x) * 4;
    if (i + 4 <= E) {
        int4 s = *(const int4*)(src + i);
        int4 d = *(const int4*)(dst + i);
        atomicAdd(&g_cnt[s.x], 1); atomicAdd(&g_cnt[s.y], 1);
        atomicAdd(&g_cnt[s.z], 1); atomicAdd(&g_cnt[s.w], 1);
        atomicAdd(&g_cnt[NN + d.x], 1); atomicAdd(&g_cnt[NN + d.y], 1);
        atomicAdd(&g_cnt[NN + d.z], 1); atomicAdd(&g_cnt[NN + d.w], 1);
    } else {
        for (int j = i; j < E; j++) {
            atomicAdd(&g_cnt[src[j]], 1);
            atomicAdd(&g_cnt[NN + dst[j]], 1);
        }
    }
}

// ---------------------------------------------------------------------------
// Scan + norm fused (R4-proven)
// ---------------------------------------------------------------------------
__global__ void __launch_bounds__(256) scan_norm_kernel(int N) {
    __shared__ int wsum[8];
    __shared__ int sbase;
    int i = blockIdx.x * 256 + threadIdx.x;
    int lane = threadIdx.x & 31, wid = threadIdx.x >> 5;

    int cin = (i < N) ? g_cnt[NN + i] : 0;
    int x = cin;
#pragma unroll
    for (int o = 1; o < 32; o <<= 1) {
        int n = __shfl_up_sync(0xffffffffu, x, o);
        if (lane >= o) x += n;
    }
    if (lane == 31) wsum[wid] = x;
    __syncthreads();
    if (threadIdx.x == 0) {
        int run = 0;
#pragma unroll
        for (int w = 0; w < 8; w++) { run += wsum[w]; wsum[w] = run; }
        sbase = atomicAdd(&g_cnt[2 * NN], run);
    }
    __syncthreads();
    int excl = x - cin + (wid > 0 ? wsum[wid - 1] : 0) + sbase;
    if (i < N) {
        g_off[i] = excl;
        g_cursor[i] = excl;
        g_nsrc[i] = rsqrtf(fmaxf((float)g_cnt[i], 1.0f));
        g_ndst[i] = rsqrtf(fmaxf((float)cin, 1.0f));
    }
}

// ---------------------------------------------------------------------------
// Fill CSR: 1 edge per thread (R4-proven)
// ---------------------------------------------------------------------------
__global__ void fill_kernel(const int* __restrict__ src, const int* __restrict__ dst, int E) {
    int i = blockIdx.x * blockDim.x + threadIdx.x;
    if (i < E) {
        int p = atomicAdd(&g_cursor[dst[i]], 1);
        g_csr[p] = src[i];
    }
}

// ---------------------------------------------------------------------------
// GEMM1 (wmma HMMA, R9-proven): x16 = fp16( (feat * nsrc) @ W1 )
// ---------------------------------------------------------------------------
__global__ void __launch_bounds__(256) gemm1_kernel(const float* __restrict__ feat,
                                                    const float* __restrict__ W1, int N) {
    __shared__ __align__(32) __half As[64][136];
    __shared__ __align__(32) __half Bs[128][72];
    int tid = threadIdx.x;
    int w = tid >> 5;
    int r0 = blockIdx.x * 64;

    for (int idx = tid; idx < 2048; idx += 256) {
        int r = idx >> 5;
        int c4 = idx & 31;
        int row = r0 + r;
        float4 v = make_float4(0.f, 0.f, 0.f, 0.f);
        float s = 0.f;
        if (row < N) {
            v = ((const float4*)(feat + (size_t)row * FD))[c4];
            s = g_nsrc[row];
        }
        __half2 h0 = __floats2half2_rn(v.x * s, v.y * s);
        __half2 h1 = __floats2half2_rn(v.z * s, v.w * s);
        uint2 pk; pk.x = *(unsigned*)&h0; pk.y = *(unsigned*)&h1;
        *(uint2*)&As[r][c4 * 4] = pk;
    }
    for (int idx = tid; idx < 2048; idx += 256) {
        int k = idx >> 4;
        int c4 = idx & 15;
        float4 v = ((const float4*)(W1 + (size_t)k * HD))[c4];
        __half2 h0 = __floats2half2_rn(v.x, v.y);
        __half2 h1 = __floats2half2_rn(v.z, v.w);
        uint2 pk; pk.x = *(unsigned*)&h0; pk.y = *(unsigned*)&h1;
        *(uint2*)&Bs[k][c4 * 4] = pk;
    }
    __syncthreads();

    int rg = w >> 1;
    int cg = (w & 1) * 2;
    wmma::fragment<wmma::accumulator, 16, 16, 16, float> c0, c1;
    wmma::fill_fragment(c0, 0.0f);
    wmma::fill_fragment(c1, 0.0f);
#pragma unroll
    for (int k = 0; k < 8; k++) {
        wmma::fragment<wmma::matrix_a, 16, 16, 16, __half, wmma::row_major> a;
        wmma::fragment<wmma::matrix_b, 16, 16, 16, __half, wmma::row_major> b0, b1;
        wmma::load_matrix_sync(a, &As[rg * 16][k * 16], 136);
        wmma::load_matrix_sync(b0, &Bs[k * 16][cg * 16], 72);
        wmma::load_matrix_sync(b1, &Bs[k * 16][(cg + 1) * 16], 72);
        wmma::mma_sync(c0, a, b0, c0);
        wmma::mma_sync(c1, a, b1, c1);
    }
    __syncthreads();

    float* Cs = (float*)&As[0][0];
    wmma::store_matrix_sync(Cs + (rg * 16) * 68 + cg * 16, c0, 68, wmma::mem_row_major);
    wmma::store_matrix_sync(Cs + (rg * 16) * 68 + (cg + 1) * 16, c1, 68, wmma::mem_row_major);
    __syncthreads();

    for (int idx = tid; idx < 1024; idx += 256) {
        int r = idx >> 4;
        int c4 = idx & 15;
        int row = r0 + r;
        if (row < N) {
            const float* p = Cs + r * 68 + c4 * 4;
            __half2 h0 = __floats2half2_rn(p[0], p[1]);
            __half2 h1 = __floats2half2_rn(p[2], p[3]);
            uint2 pk; pk.x = *(unsigned*)&h0; pk.y = *(unsigned*)&h1;
            *(uint2*)(g_x16 + (size_t)row * HD + c4 * 4) = pk;
        }
    }
}

// ---------------------------------------------------------------------------
// Shuffle-batched gather core (~1 LDG per edge) — R4-proven
// ---------------------------------------------------------------------------
__device__ __forceinline__ void gather_row(const __half* __restrict__ X,
                                           int beg, int end, int lane,
                                           float& ax, float& ay) {
    ax = 0.f; ay = 0.f;
    int j = beg;
    for (; j + 32 <= end; j += 32) {
        int s = g_csr[j + lane];
#pragma unroll
        for (int t = 0; t < 32; t += 4) {
            int r0 = __shfl_sync(0xffffffffu, s, t + 0);
            int r1 = __shfl_sync(0xffffffffu, s, t + 1);
            int r2 = __shfl_sync(0xffffffffu, s, t + 2);
            int r3 = __shfl_sync(0xffffffffu, s, t + 3);
            float2 v0 = __half22float2(*(const __half2*)(X + (size_t)r0 * HD + lane * 2));
            float2 v1 = __half22float2(*(const __half2*)(X + (size_t)r1 * HD + lane * 2));
            float2 v2 = __half22float2(*(const __half2*)(X + (size_t)r2 * HD + lane * 2));
            float2 v3 = __half22float2(*(const __half2*)(X + (size_t)r3 * HD + lane * 2));
            ax += (v0.x + v1.x) + (v2.x + v3.x);
            ay += (v0.y + v1.y) + (v2.y + v3.y);
        }
    }
    int rem = end - j;
    if (rem > 0) {
        int s = (lane < rem) ? g_csr[j + lane] : 0;
        int t = 0;
        for (; t + 4 <= rem; t += 4) {
            int r0 = __shfl_sync(0xffffffffu, s, t + 0);
            int r1 = __shfl_sync(0xffffffffu, s, t + 1);
            int r2 = __shfl_sync(0xffffffffu, s, t + 2);
            int r3 = __shfl_sync(0xffffffffu, s, t + 3);
            float2 v0 = __half22float2(*(const __half2*)(X + (size_t)r0 * HD + lane * 2));
            float2 v1 = __half22float2(*(const __half2*)(X + (size_t)r1 * HD + lane * 2));
            float2 v2 = __half22float2(*(const __half2*)(X + (size_t)r2 * HD + lane * 2));
            float2 v3 = __half22float2(*(const __half2*)(X + (size_t)r3 * HD + lane * 2));
            ax += (v0.x + v1.x) + (v2.x + v3.x);
            ay += (v0.y + v1.y) + (v2.y + v3.y);
        }
        for (; t < rem; t++) {
            int r = __shfl_sync(0xffffffffu, s, t);
            float2 v = __half22float2(*(const __half2*)(X + (size_t)r * HD + lane * 2));
            ax += v.x; ay += v.y;
        }
    }
}

__global__ void __launch_bounds__(256) gather1_kernel(const float* __restrict__ b1, int N) {
    int warp = (blockIdx.x * blockDim.x + threadIdx.x) >> 5;
    int lane = threadIdx.x & 31;
    if (warp >= N) return;
    int beg = g_off[warp];
    int end = beg + g_cnt[NN + warp];

    float ax, ay;
    gather_row(g_x16, beg, end, lane, ax, ay);

    float nd = g_ndst[warp];
    float ns = g_nsrc[warp];
    float2 b = *(const float2*)(b1 + lane * 2);
    float ox = fmaxf(ax * nd + b.x, 0.f) * ns;
    float oy = fmaxf(ay * nd + b.y, 0.f) * ns;
    *(__half2*)(g_y16 + (size_t)warp * HD + lane * 2) = __floats2half2_rn(ox, oy);
}

// ---------------------------------------------------------------------------
// Fused gather2 + final (wmma HMMA dual-GEMM):
//   a[n] = fp16( (sum_{s in in(n)} y16[s]) * ndst[n] )  gathered into smem As
//   C = a @ [W_mu | W_sig]  (fp32 accumulate)
//   z = (mu + b_mu) + noise * exp(ls + b_sig)
// ---------------------------------------------------------------------------
__global__ void __launch_bounds__(256) final_fused_kernel(const float* __restrict__ noise,
                                                          const float* __restrict__ W_mu,
                                                          const float* __restrict__ b_mu,
                                                          const float* __restrict__ W_sig,
                                                          const float* __restrict__ b_sig,
                                                          float* __restrict__ out, int N) {
    __shared__ __align__(32) char sbuf[64 * 132 * 4];    // 33792 B union
    __half* As = (__half*)sbuf;                          // [64][72]  = 9216 B
    __half* Bs = (__half*)(sbuf + 9216);                 // [64][136] = 17408 B
    float*  Cs = (float*)sbuf;                           // [64][132] (after mma)
    int tid = threadIdx.x;
    int w = tid >> 5, lane = tid & 31;
    int r0 = blockIdx.x * 64;

    // B: [W_mu | W_sig] -> fp16, 64 rows x 128 cols (fast, do first)
    for (int idx = tid; idx < 2048; idx += 256) {
        int k = idx >> 5;
        int c4 = idx & 31;
        float4 v = (c4 < 16) ? ((const float4*)(W_mu + (size_t)k * HD))[c4]
                             : ((const float4*)(W_sig + (size_t)k * HD))[c4 - 16];
        __half2 h0 = __floats2half2_rn(v.x, v.y);
        __half2 h1 = __floats2half2_rn(v.z, v.w);
        uint2 pk; pk.x = *(unsigned*)&h0; pk.y = *(unsigned*)&h1;
        *(uint2*)&Bs[k * 136 + c4 * 4] = pk;
    }

    // Gather phase: warp w gathers rows [w*8, w*8+8) of the A tile
#pragma unroll
    for (int rr = 0; rr < 8; rr++) {
        int r = w * 8 + rr;
        int node = r0 + r;
        float ax = 0.f, ay = 0.f;
        if (node < N) {
            int beg = g_off[node];
            int end = beg + g_cnt[NN + node];
            gather_row(g_y16, beg, end, lane, ax, ay);
            float nd = g_ndst[node];
            ax *= nd; ay *= nd;
        }
        *(__half2*)&As[r * 72 + lane * 2] = __floats2half2_rn(ax, ay);
    }
    __syncthreads();

    int rg = w >> 1;
    int ch = (w & 1) * 4;
    wmma::fragment<wmma::accumulator, 16, 16, 16, float> c[4];
#pragma unroll
    for (int f = 0; f < 4; f++) wmma::fill_fragment(c[f], 0.0f);
#pragma unroll
    for (int k = 0; k < 4; k++) {
        wmma::fragment<wmma::matrix_a, 16, 16, 16, __half, wmma::row_major> a;
        wmma::load_matrix_sync(a, &As[rg * 16 * 72 + k * 16], 72);
#pragma unroll
        for (int f = 0; f < 4; f++) {
            wmma::fragment<wmma::matrix_b, 16, 16, 16, __half, wmma::row_major> b;
            wmma::load_matrix_sync(b, &Bs[k * 16 * 136 + (ch + f) * 16], 136);
            wmma::mma_sync(c[f], a, b, c[f]);
        }
    }
    __syncthreads();
#pragma unroll
    for (int f = 0; f < 4; f++)
        wmma::store_matrix_sync(Cs + (rg * 16) * 132 + (ch + f) * 16, c[f], 132,
                                wmma::mem_row_major);
    __syncthreads();

    // Epilogue: 64 rows x 64 outputs
    int tx = tid & 15, ty = tid >> 4;
    float4 bm = *(const float4*)(b_mu + tx * 4);
    float4 bsg = *(const float4*)(b_sig + tx * 4);
#pragma unroll
    for (int i = 0; i < 4; i++) {
        int r = ty * 4 + i;
        int row = r0 + r;
        if (row < N) {
            const float* pm = Cs + r * 132 + tx * 4;
            const float* ps = Cs + r * 132 + 64 + tx * 4;
            float4 nz = *(const float4*)(noise + (size_t)row * HD + tx * 4);
            float4 o;
            o.x = (pm[0] + bm.x) + nz.x * expf(ps[0] + bsg.x);
            o.y = (pm[1] + bm.y) + nz.y * expf(ps[1] + bsg.y);
            o.z = (pm[2] + bm.z) + nz.z * expf(ps[2] + bsg.z);
            o.w = (pm[3] + bm.w) + nz.w * expf(ps[3] + bsg.w);
            *(float4*)(out + (size_t)row * HD + tx * 4) = o;
        }
    }
}

// ---------------------------------------------------------------------------
// Launch — R4/R9 structure, gather2 fused into final
// ---------------------------------------------------------------------------
static cudaStream_t s2 = nullptr;
static cudaEvent_t  evScan = nullptr, evGemm = nullptr;

extern "C" void kernel_launch(void* const* d_in, const int* in_sizes, int n_in,
                              void* d_out, int out_size) {
    const float* feat  = (const float*)d_in[0];
    const int*   src   = (const int*)d_in[1];
    const int*   dst   = (const int*)d_in[2];
    const float* noise = (const float*)d_in[3];
    const float* W1    = (const float*)d_in[4];
    const float* b1    = (const float*)d_in[5];
    const float* W_mu  = (const float*)d_in[6];
    const float* b_mu  = (const float*)d_in[7];
    const float* W_sig = (const float*)d_in[8];
    const float* b_sig = (const float*)d_in[9];

    int N = in_sizes[0] / FD;
    int E = in_sizes[1];

    if (s2 == nullptr) {
        cudaStreamCreateWithFlags(&s2, cudaStreamNonBlocking);
        cudaEventCreateWithFlags(&evScan, cudaEventDisableTiming);
        cudaEventCreateWithFlags(&evGemm, cudaEventDisableTiming);
    }

    void* p_cnt;
    cudaGetSymbolAddress(&p_cnt, g_cnt);
    cudaMemsetAsync(p_cnt, 0, sizeof(int) * (2 * NN + 32));

    deg_kernel<<<(E / 4 + 255) / 256, 256>>>(src, dst, E);
    scan_norm_kernel<<<(N + 255) / 256, 256>>>(N);
    cudaEventRecord(evScan, 0);

    // gemm1 (needs nsrc only) overlaps with fill on stream 2
    cudaStreamWaitEvent(s2, evScan, 0);
    gemm1_kernel<<<(N + 63) / 64, 256, 0, s2>>>(feat, W1, N);
    cudaEventRecord(evGemm, s2);

    fill_kernel<<<(E + 255) / 256, 256>>>(src, dst, E);
    cudaStreamWaitEvent(0, evGemm, 0);

    int gblocks = (N * 32 + 255) / 256;
    gather1_kernel<<<gblocks, 256>>>(b1, N);

    final_fused_kernel<<<(N + 63) / 64, 256>>>(noise, W_mu, b_mu, W_sig, b_sig,
                                               (float*)d_out, N);
}

// round 11
// speedup vs baseline: 1.0478x; 1.0478x over previous
#include <cuda_runtime.h>
#include <cuda_fp16.h>
#include <mma.h>
#include <math.h>

using namespace nvcuda;

#define NN 100000
#define EE 1600000
#define FD 128
#define HD 64

// Scratch (device globals)
__device__ int    g_cnt[2 * NN + 32];       // [0..NN)=out, [NN..2NN)=in, [2NN]=scan ticket
__device__ float  g_nsrc[NN];
__device__ float  g_ndst[NN];
__device__ int    g_off[NN];
__device__ int    g_cursor[NN];
__device__ int    g_csr[EE];
__device__ __half g_x16[(size_t)NN * HD];   // x = (feat*nsrc)@W1 (fp16)
__device__ __half g_y16[(size_t)NN * HD];   // y = relu(agg1*ndst+b1)*nsrc (fp16)
__device__ __half g_a16[(size_t)NN * HD];   // agg2*ndst (fp16, wmma A input)

// ---------------------------------------------------------------------------
// Degrees (R4-proven: 4 edges/thread)
// ---------------------------------------------------------------------------
__global__ void deg_kernel(const int* __restrict__ src, const int* __restrict__ dst, int E) {
    int i = (blockIdx.x * blockDim.x + threadIdx.x) * 4;
    if (i + 4 <= E) {
        int4 s = *(const int4*)(src + i);
        int4 d = *(const int4*)(dst + i);
        atomicAdd(&g_cnt[s.x], 1); atomicAdd(&g_cnt[s.y], 1);
        atomicAdd(&g_cnt[s.z], 1); atomicAdd(&g_cnt[s.w], 1);
        atomicAdd(&g_cnt[NN + d.x], 1); atomicAdd(&g_cnt[NN + d.y], 1);
        atomicAdd(&g_cnt[NN + d.z], 1); atomicAdd(&g_cnt[NN + d.w], 1);
    } else {
        for (int j = i; j < E; j++) {
            atomicAdd(&g_cnt[src[j]], 1);
            atomicAdd(&g_cnt[NN + dst[j]], 1);
        }
    }
}

// ---------------------------------------------------------------------------
// Scan + norm fused (R4-proven)
// ---------------------------------------------------------------------------
__global__ void __launch_bounds__(256) scan_norm_kernel(int N) {
    __shared__ int wsum[8];
    __shared__ int sbase;
    int i = blockIdx.x * 256 + threadIdx.x;
    int lane = threadIdx.x & 31, wid = threadIdx.x >> 5;

    int cin = (i < N) ? g_cnt[NN + i] : 0;
    int x = cin;
#pragma unroll
    for (int o = 1; o < 32; o <<= 1) {
        int n = __shfl_up_sync(0xffffffffu, x, o);
        if (lane >= o) x += n;
    }
    if (lane == 31) wsum[wid] = x;
    __syncthreads();
    if (threadIdx.x == 0) {
        int run = 0;
#pragma unroll
        for (int w = 0; w < 8; w++) { run += wsum[w]; wsum[w] = run; }
        sbase = atomicAdd(&g_cnt[2 * NN], run);
    }
    __syncthreads();
    int excl = x - cin + (wid > 0 ? wsum[wid - 1] : 0) + sbase;
    if (i < N) {
        g_off[i] = excl;
        g_cursor[i] = excl;
        g_nsrc[i] = rsqrtf(fmaxf((float)g_cnt[i], 1.0f));
        g_ndst[i] = rsqrtf(fmaxf((float)cin, 1.0f));
    }
}

// ---------------------------------------------------------------------------
// Fill CSR: 1 edge per thread (R4-proven)
// ---------------------------------------------------------------------------
__global__ void fill_kernel(const int* __restrict__ src, const int* __restrict__ dst, int E) {
    int i = blockIdx.x * blockDim.x + threadIdx.x;
    if (i < E) {
        int p = atomicAdd(&g_cursor[dst[i]], 1);
        g_csr[p] = src[i];
    }
}

// ---------------------------------------------------------------------------
// GEMM1 (wmma HMMA, R9-proven): x16 = fp16( (feat * nsrc) @ W1 )
// ---------------------------------------------------------------------------
__global__ void __launch_bounds__(256) gemm1_kernel(const float* __restrict__ feat,
                                                    const float* __restrict__ W1, int N) {
    __shared__ __align__(32) __half As[64][136];
    __shared__ __align__(32) __half Bs[128][72];
    int tid = threadIdx.x;
    int w = tid >> 5;
    int r0 = blockIdx.x * 64;

    for (int idx = tid; idx < 2048; idx += 256) {
        int r = idx >> 5;
        int c4 = idx & 31;
        int row = r0 + r;
        float4 v = make_float4(0.f, 0.f, 0.f, 0.f);
        float s = 0.f;
        if (row < N) {
            v = ((const float4*)(feat + (size_t)row * FD))[c4];
            s = g_nsrc[row];
        }
        __half2 h0 = __floats2half2_rn(v.x * s, v.y * s);
        __half2 h1 = __floats2half2_rn(v.z * s, v.w * s);
        uint2 pk; pk.x = *(unsigned*)&h0; pk.y = *(unsigned*)&h1;
        *(uint2*)&As[r][c4 * 4] = pk;
    }
    for (int idx = tid; idx < 2048; idx += 256) {
        int k = idx >> 4;
        int c4 = idx & 15;
        float4 v = ((const float4*)(W1 + (size_t)k * HD))[c4];
        __half2 h0 = __floats2half2_rn(v.x, v.y);
        __half2 h1 = __floats2half2_rn(v.z, v.w);
        uint2 pk; pk.x = *(unsigned*)&h0; pk.y = *(unsigned*)&h1;
        *(uint2*)&Bs[k][c4 * 4] = pk;
    }
    __syncthreads();

    int rg = w >> 1;
    int cg = (w & 1) * 2;
    wmma::fragment<wmma::accumulator, 16, 16, 16, float> c0, c1;
    wmma::fill_fragment(c0, 0.0f);
    wmma::fill_fragment(c1, 0.0f);
#pragma unroll
    for (int k = 0; k < 8; k++) {
        wmma::fragment<wmma::matrix_a, 16, 16, 16, __half, wmma::row_major> a;
        wmma::fragment<wmma::matrix_b, 16, 16, 16, __half, wmma::row_major> b0, b1;
        wmma::load_matrix_sync(a, &As[rg * 16][k * 16], 136);
        wmma::load_matrix_sync(b0, &Bs[k * 16][cg * 16], 72);
        wmma::load_matrix_sync(b1, &Bs[k * 16][(cg + 1) * 16], 72);
        wmma::mma_sync(c0, a, b0, c0);
        wmma::mma_sync(c1, a, b1, c1);
    }
    __syncthreads();

    float* Cs = (float*)&As[0][0];
    wmma::store_matrix_sync(Cs + (rg * 16) * 68 + cg * 16, c0, 68, wmma::mem_row_major);
    wmma::store_matrix_sync(Cs + (rg * 16) * 68 + (cg + 1) * 16, c1, 68, wmma::mem_row_major);
    __syncthreads();

    for (int idx = tid; idx < 1024; idx += 256) {
        int r = idx >> 4;
        int c4 = idx & 15;
        int row = r0 + r;
        if (row < N) {
            const float* p = Cs + r * 68 + c4 * 4;
            __half2 h0 = __floats2half2_rn(p[0], p[1]);
            __half2 h1 = __floats2half2_rn(p[2], p[3]);
            uint2 pk; pk.x = *(unsigned*)&h0; pk.y = *(unsigned*)&h1;
            *(uint2*)(g_x16 + (size_t)row * HD + c4 * 4) = pk;
        }
    }
}

// ---------------------------------------------------------------------------
// Shuffle-batched gather core (~1 LDG per edge) — R4-proven
// ---------------------------------------------------------------------------
__device__ __forceinline__ void gather_row(const __half* __restrict__ X,
                                           int beg, int end, int lane,
                                           float& ax, float& ay) {
    ax = 0.f; ay = 0.f;
    int j = beg;
    for (; j + 32 <= end; j += 32) {
        int s = g_csr[j + lane];
#pragma unroll
        for (int t = 0; t < 32; t += 4) {
            int r0 = __shfl_sync(0xffffffffu, s, t + 0);
            int r1 = __shfl_sync(0xffffffffu, s, t + 1);
            int r2 = __shfl_sync(0xffffffffu, s, t + 2);
            int r3 = __shfl_sync(0xffffffffu, s, t + 3);
            float2 v0 = __half22float2(*(const __half2*)(X + (size_t)r0 * HD + lane * 2));
            float2 v1 = __half22float2(*(const __half2*)(X + (size_t)r1 * HD + lane * 2));
            float2 v2 = __half22float2(*(const __half2*)(X + (size_t)r2 * HD + lane * 2));
            float2 v3 = __half22float2(*(const __half2*)(X + (size_t)r3 * HD + lane * 2));
            ax += (v0.x + v1.x) + (v2.x + v3.x);
            ay += (v0.y + v1.y) + (v2.y + v3.y);
        }
    }
    int rem = end - j;
    if (rem > 0) {
        int s = (lane < rem) ? g_csr[j + lane] : 0;
        int t = 0;
        for (; t + 4 <= rem; t += 4) {
            int r0 = __shfl_sync(0xffffffffu, s, t + 0);
            int r1 = __shfl_sync(0xffffffffu, s, t + 1);
            int r2 = __shfl_sync(0xffffffffu, s, t + 2);
            int r3 = __shfl_sync(0xffffffffu, s, t + 3);
            float2 v0 = __half22float2(*(const __half2*)(X + (size_t)r0 * HD + lane * 2));
            float2 v1 = __half22float2(*(const __half2*)(X + (size_t)r1 * HD + lane * 2));
            float2 v2 = __half22float2(*(const __half2*)(X + (size_t)r2 * HD + lane * 2));
            float2 v3 = __half22float2(*(const __half2*)(X + (size_t)r3 * HD + lane * 2));
            ax += (v0.x + v1.x) + (v2.x + v3.x);
            ay += (v0.y + v1.y) + (v2.y + v3.y);
        }
        for (; t < rem; t++) {
            int r = __shfl_sync(0xffffffffu, s, t);
            float2 v = __half22float2(*(const __half2*)(X + (size_t)r * HD + lane * 2));
            ax += v.x; ay += v.y;
        }
    }
}

__global__ void __launch_bounds__(256) gather1_kernel(const float* __restrict__ b1, int N) {
    int warp = (blockIdx.x * blockDim.x + threadIdx.x) >> 5;
    int lane = threadIdx.x & 31;
    if (warp >= N) return;
    int beg = g_off[warp];
    int end = beg + g_cnt[NN + warp];

    float ax, ay;
    gather_row(g_x16, beg, end, lane, ax, ay);

    float nd = g_ndst[warp];
    float ns = g_nsrc[warp];
    float2 b = *(const float2*)(b1 + lane * 2);
    float ox = fmaxf(ax * nd + b.x, 0.f) * ns;
    float oy = fmaxf(ay * nd + b.y, 0.f) * ns;
    *(__half2*)(g_y16 + (size_t)warp * HD + lane * 2) = __floats2half2_rn(ox, oy);
}

__global__ void __launch_bounds__(256) gather2_kernel(int N) {
    int warp = (blockIdx.x * blockDim.x + threadIdx.x) >> 5;
    int lane = threadIdx.x & 31;
    if (warp >= N) return;
    int beg = g_off[warp];
    int end = beg + g_cnt[NN + warp];

    float ax, ay;
    gather_row(g_y16, beg, end, lane, ax, ay);

    float nd = g_ndst[warp];
    *(__half2*)(g_a16 + (size_t)warp * HD + lane * 2) = __floats2half2_rn(ax * nd, ay * nd);
}

// ---------------------------------------------------------------------------
// Final (wmma HMMA dual-GEMM, R9-proven) with __expf epilogue:
//   C = a16 @ [W_mu | W_sig], fp32 accumulate;
//   z = (mu + b_mu) + noise * __expf(ls + b_sig)
// ---------------------------------------------------------------------------
__global__ void __launch_bounds__(256) final_kernel(const float* __restrict__ noise,
                                                    const float* __restrict__ W_mu,
                                                    const float* __restrict__ b_mu,
                                                    const float* __restrict__ W_sig,
                                                    const float* __restrict__ b_sig,
                                                    float* __restrict__ out, int N) {
    __shared__ __align__(32) char sbuf[64 * 132 * 4];    // 33792 B union
    __half* As = (__half*)sbuf;                          // [64][72]  = 9216 B
    __half* Bs = (__half*)(sbuf + 9216);                 // [64][136] = 17408 B
    float*  Cs = (float*)sbuf;                           // [64][132] (after mma)
    int tid = threadIdx.x;
    int w = tid >> 5;
    int r0 = blockIdx.x * 64;

    // A: g_a16 rows (fp16), 64 x 16 uint2
    for (int idx = tid; idx < 1024; idx += 256) {
        int r = idx >> 4;
        int c4 = idx & 15;
        int row = r0 + r;
        uint2 pk = make_uint2(0u, 0u);
        if (row < N) pk = *(const uint2*)(g_a16 + (size_t)row * HD + c4 * 4);
        *(uint2*)&As[r * 72 + c4 * 4] = pk;
    }
    // B: [W_mu | W_sig] -> fp16, 64 rows x 128 cols. 2048 float4.
    for (int idx = tid; idx < 2048; idx += 256) {
        int k = idx >> 5;
        int c4 = idx & 31;
        float4 v = (c4 < 16) ? ((const float4*)(W_mu + (size_t)k * HD))[c4]
                             : ((const float4*)(W_sig + (size_t)k * HD))[c4 - 16];
        __half2 h0 = __floats2half2_rn(v.x, v.y);
        __half2 h1 = __floats2half2_rn(v.z, v.w);
        uint2 pk; pk.x = *(unsigned*)&h0; pk.y = *(unsigned*)&h1;
        *(uint2*)&Bs[k * 136 + c4 * 4] = pk;
    }
    __syncthreads();

    int rg = w >> 1;
    int ch = (w & 1) * 4;
    wmma::fragment<wmma::accumulator, 16, 16, 16, float> c[4];
#pragma unroll
    for (int f = 0; f < 4; f++) wmma::fill_fragment(c[f], 0.0f);
#pragma unroll
    for (int k = 0; k < 4; k++) {
        wmma::fragment<wmma::matrix_a, 16, 16, 16, __half, wmma::row_major> a;
        wmma::load_matrix_sync(a, &As[rg * 16 * 72 + k * 16], 72);
#pragma unroll
        for (int f = 0; f < 4; f++) {
            wmma::fragment<wmma::matrix_b, 16, 16, 16, __half, wmma::row_major> b;
            wmma::load_matrix_sync(b, &Bs[k * 16 * 136 + (ch + f) * 16], 136);
            wmma::mma_sync(c[f], a, b, c[f]);
        }
    }
    __syncthreads();
#pragma unroll
    for (int f = 0; f < 4; f++)
        wmma::store_matrix_sync(Cs + (rg * 16) * 132 + (ch + f) * 16, c[f], 132,
                                wmma::mem_row_major);
    __syncthreads();

    // Epilogue: 64 rows x 64 outputs, fast exp (MUFU.EX2)
    int tx = tid & 15, ty = tid >> 4;
    float4 bm = *(const float4*)(b_mu + tx * 4);
    float4 bsg = *(const float4*)(b_sig + tx * 4);
#pragma unroll
    for (int i = 0; i < 4; i++) {
        int r = ty * 4 + i;
        int row = r0 + r;
        if (row < N) {
            const float* pm = Cs + r * 132 + tx * 4;
            const float* ps = Cs + r * 132 + 64 + tx * 4;
            float4 nz = *(const float4*)(noise + (size_t)row * HD + tx * 4);
            float4 o;
            o.x = (pm[0] + bm.x) + nz.x * __expf(ps[0] + bsg.x);
            o.y = (pm[1] + bm.y) + nz.y * __expf(ps[1] + bsg.y);
            o.z = (pm[2] + bm.z) + nz.z * __expf(ps[2] + bsg.z);
            o.w = (pm[3] + bm.w) + nz.w * __expf(ps[3] + bsg.w);
            *(float4*)(out + (size_t)row * HD + tx * 4) = o;
        }
    }
}

// ---------------------------------------------------------------------------
// Launch — exact R9 structure
// ---------------------------------------------------------------------------
static cudaStream_t s2 = nullptr;
static cudaEvent_t  evScan = nullptr, evGemm = nullptr;

extern "C" void kernel_launch(void* const* d_in, const int* in_sizes, int n_in,
                              void* d_out, int out_size) {
    const float* feat  = (const float*)d_in[0];
    const int*   src   = (const int*)d_in[1];
    const int*   dst   = (const int*)d_in[2];
    const float* noise = (const float*)d_in[3];
    const float* W1    = (const float*)d_in[4];
    const float* b1    = (const float*)d_in[5];
    const float* W_mu  = (const float*)d_in[6];
    const float* b_mu  = (const float*)d_in[7];
    const float* W_sig = (const float*)d_in[8];
    const float* b_sig = (const float*)d_in[9];

    int N = in_sizes[0] / FD;
    int E = in_sizes[1];

    if (s2 == nullptr) {
        cudaStreamCreateWithFlags(&s2, cudaStreamNonBlocking);
        cudaEventCreateWithFlags(&evScan, cudaEventDisableTiming);
        cudaEventCreateWithFlags(&evGemm, cudaEventDisableTiming);
    }

    void* p_cnt;
    cudaGetSymbolAddress(&p_cnt, g_cnt);
    cudaMemsetAsync(p_cnt, 0, sizeof(int) * (2 * NN + 32));

    deg_kernel<<<(E / 4 + 255) / 256, 256>>>(src, dst, E);
    scan_norm_kernel<<<(N + 255) / 256, 256>>>(N);
    cudaEventRecord(evScan, 0);

    // gemm1 (needs nsrc only) overlaps with fill on stream 2
    cudaStreamWaitEvent(s2, evScan, 0);
    gemm1_kernel<<<(N + 63) / 64, 256, 0, s2>>>(feat, W1, N);
    cudaEventRecord(evGemm, s2);

    fill_kernel<<<(E + 255) / 256, 256>>>(src, dst, E);
    cudaStreamWaitEvent(0, evGemm, 0);

    int gblocks = (N * 32 + 255) / 256;
    gather1_kernel<<<gblocks, 256>>>(b1, N);
    gather2_kernel<<<gblocks, 256>>>(N);

    final_kernel<<<(N + 63) / 64, 256>>>(noise, W_mu, b_mu, W_sig, b_sig,
                                         (float*)d_out, N);
}